// round 3
// baseline (speedup 1.0000x reference)
#include <cuda_runtime.h>
#include <stdint.h>
#include <stddef.h>

#define BB 32768
#define MM 8192
#define GG 128
#define NCELL (GG*GG)

typedef unsigned long long ull;

static __device__ __forceinline__ float f_inf() { return __int_as_float(0x7f800000); }

static __device__ __forceinline__ void ffma2(ull &d, ull a, ull b) {
    asm("fma.rn.f32x2 %0, %1, %2, %0;" : "+l"(d) : "l"(a), "l"(b));
}

// ---------------- scratch (device globals; no allocation allowed) ----------------
__device__ float  g_X0p[BB*80];     // padded knn_feat (66 -> 80, zero pad)
__device__ float  g_X1[BB*128];
__device__ float  g_X2[BB*256];
__device__ float  g_X3[BB*512];
__device__ float  g_X4[BB*128];
__device__ float  g_X5[BB*64];
__device__ float  g_psum[128*512];  // per-256-rowblock column sums (max N=512)
__device__ float  g_psq [128*512];
__device__ float  g_scale[512];
__device__ float  g_shift[512];
__device__ int    g_cellCount[NCELL];
__device__ int    g_cellFill [NCELL];
__device__ int    g_cellStart[NCELL+1];
__device__ float4 g_packed[MM];     // (mx, my, mx^2+my^2, orig_idx)
__device__ float  g_W1p[80*128];    // zero-padded w1

// ---------------- grid build ----------------
__global__ void zero_cells_kernel() {
    int i = blockIdx.x*blockDim.x + threadIdx.x;
    if (i < NCELL) { g_cellCount[i] = 0; g_cellFill[i] = 0; }
}

__device__ __forceinline__ int cell_of(float v) {
    const float GMINF = -6.0f;
    const float INVH  = GG / 12.0f;
    int c = (int)floorf((v - GMINF) * INVH);
    return min(max(c, 0), GG-1);
}

__global__ void count_kernel(const float* __restrict__ mc) {
    int i = blockIdx.x*blockDim.x + threadIdx.x;
    if (i >= MM) return;
    int cx = cell_of(mc[2*i]);
    int cy = cell_of(mc[2*i+1]);
    atomicAdd(&g_cellCount[cy*GG + cx], 1);
}

__global__ void scan_kernel() {
    __shared__ int sums[256];
    int t = threadIdx.x;
    const int per = NCELL / 256;
    int base = t * per;
    int s = 0;
    for (int i = 0; i < per; i++) s += g_cellCount[base + i];
    sums[t] = s;
    __syncthreads();
    if (t == 0) {
        int acc = 0;
        for (int i = 0; i < 256; i++) { int v = sums[i]; sums[i] = acc; acc += v; }
    }
    __syncthreads();
    int off = sums[t];
    for (int i = 0; i < per; i++) { int v = g_cellCount[base + i]; g_cellStart[base + i] = off; off += v; }
    if (t == 255) g_cellStart[NCELL] = off;
}

__global__ void scatter_kernel(const float* __restrict__ mc) {
    int i = blockIdx.x*blockDim.x + threadIdx.x;
    if (i >= MM) return;
    float x = mc[2*i], y = mc[2*i+1];
    int cx = cell_of(x), cy = cell_of(y);
    int c = cy*GG + cx;
    int slot = g_cellStart[c] + atomicAdd(&g_cellFill[c], 1);
    float sm = __fadd_rn(__fmul_rn(x, x), __fmul_rn(y, y));
    g_packed[slot] = make_float4(x, y, sm, __int_as_float(i));
}

__global__ void padw1_kernel(const float* __restrict__ w1) {
    int i = blockIdx.x*blockDim.x + threadIdx.x;
    if (i >= 80*128) return;
    int row = i / 128, col = i % 128;
    g_W1p[i] = (row < 66) ? w1[row*128 + col] : 0.0f;
}

// ---------------- KNN ----------------
#define SCAN_RANGE(S_, E_)                                                        \
    for (int j_ = (S_); j_ < (E_); j_++) {                                        \
        float4 v_ = g_packed[j_];                                                 \
        float dot_ = __fmaf_rn(py, v_.y, __fmul_rn(px, v_.x));                    \
        float d2_  = __fmaf_rn(dot_, -2.0f, __fadd_rn(sp, v_.z));                 \
        int   mi_  = __float_as_int(v_.w);                                        \
        if (d2_ < key[15] || (d2_ == key[15] && mi_ < id[15])) {                  \
            float ck_ = d2_; int ci_ = mi_;                                       \
            _Pragma("unroll")                                                     \
            for (int t2_ = 0; t2_ < 16; t2_++) {                                  \
                bool sw_ = (ck_ < key[t2_]) || (ck_ == key[t2_] && ci_ < id[t2_]);\
                float tk_ = key[t2_]; int ti_ = id[t2_];                          \
                if (sw_) { key[t2_] = ck_; id[t2_] = ci_; ck_ = tk_; ci_ = ti_; } \
            }                                                                     \
        }                                                                         \
    }

__global__ void __launch_bounds__(256) knn_kernel(
    const float* __restrict__ pos, const float* __restrict__ mc,
    const float* __restrict__ mv, float* __restrict__ outKnn)
{
    const float GMINF = -6.0f;
    const float HCELL = 12.0f / GG;
    const float MARGIN = 1e-4f;
    int q = blockIdx.x*blockDim.x + threadIdx.x;
    if (q >= BB) return;
    float px = pos[2*q], py = pos[2*q+1];
    float sp = __fadd_rn(__fmul_rn(px, px), __fmul_rn(py, py));

    float key[16]; int id[16];
#pragma unroll
    for (int i = 0; i < 16; i++) { key[i] = f_inf(); id[i] = 0x7fffffff; }

    int cx = cell_of(px), cy = cell_of(py);

    for (int R = 0;; R++) {
        int xlo = cx - R, xhi = cx + R, ylo = cy - R, yhi = cy + R;
        int xl = max(xlo, 0), xh = min(xhi, GG-1);
        int yl = max(ylo, 0), yh = min(yhi, GG-1);
        for (int yy = yl; yy <= yh; yy++) {
            if (yy == ylo || yy == yhi) {
                int s = g_cellStart[yy*GG + xl];
                int e = g_cellStart[yy*GG + xh + 1];
                SCAN_RANGE(s, e)
            } else {
                if (xlo >= 0) {
                    int s = g_cellStart[yy*GG + xlo];
                    int e = g_cellStart[yy*GG + xlo + 1];
                    SCAN_RANGE(s, e)
                }
                if (xhi <= GG-1) {
                    int s = g_cellStart[yy*GG + xhi];
                    int e = g_cellStart[yy*GG + xhi + 1];
                    SCAN_RANGE(s, e)
                }
            }
        }
        bool full = (xlo <= 0 && ylo <= 0 && xhi >= GG-1 && yhi >= GG-1);
        float x0 = GMINF + xlo * HCELL, x1 = GMINF + (xhi + 1) * HCELL;
        float y0 = GMINF + ylo * HCELL, y1 = GMINF + (yhi + 1) * HCELL;
        float db = fminf(fminf(px - x0, x1 - px), fminf(py - y0, y1 - py));
        if (full || (db > 0.0f && db*db > key[15] + MARGIN)) break;
    }

    float* o  = outKnn + (size_t)q * 66;
    float* xo = g_X0p  + (size_t)q * 80;
    o[0] = px; o[1] = py; xo[0] = px; xo[1] = py;
#pragma unroll
    for (int n = 0; n < 16; n++) {
        int mi = id[n];
        float ax = mc[2*mi], ay = mc[2*mi+1];
        float vx = mv[2*mi], vy = mv[2*mi+1];
        o[2+4*n] = ax; o[3+4*n] = ay; o[4+4*n] = vx; o[5+4*n] = vy;
        xo[2+4*n] = ax; xo[3+4*n] = ay; xo[4+4*n] = vx; xo[5+4*n] = vy;
    }
#pragma unroll
    for (int c = 66; c < 80; c++) xo[c] = 0.0f;
}

// ---------------- FFMA2 GEMM with fused input BN+ReLU and fused column stats ----
// C[B,N] = act(A)[B,K] @ W[K,N] + bias; act = BN(scale,shift)+ReLU if BNIN.
// Also writes per-256-rowblock column sums / sumsq to g_psum/g_psq (deterministic order).
// BM=256, BK=16, 256 threads, per-thread TM=16 x TN. Accumulators are f32x2 pairs
// along M; B operands stored duplicated {w,w} in smem so 64-bit loads broadcast.
template<int BN, int TN, bool BNIN>
__global__ void __launch_bounds__(256, 1) gemm2_kernel(
    const float* __restrict__ A, const float* __restrict__ W,
    const float* __restrict__ bias, float* __restrict__ C,
    int K, int N)
{
    constexpr int BM = 256, BK = 16, TM = 16;
    constexpr int WC = BN / 16;      // W-tile cols per thread
    __shared__ float  As[BK][BM];
    __shared__ float2 Ws2[BK][BN];
    __shared__ float  sSc[512];
    __shared__ float  sSh[512];
    __shared__ float  red[16][BN];

    int tid = threadIdx.x;
    if (BNIN) {
        for (int i = tid; i < K; i += 256) { sSc[i] = g_scale[i]; sSh[i] = g_shift[i]; }
    }
    __syncthreads();

    int row0 = blockIdx.y * BM;
    int col0 = blockIdx.x * BN;
    int trow = tid >> 4, tcol = tid & 15;
    int r0 = trow * TM;
    int c0 = tcol * TN;

    ull acc[TM/2][TN];
#pragma unroll
    for (int i = 0; i < TM/2; i++)
#pragma unroll
        for (int j = 0; j < TN; j++) acc[i][j] = 0ull;

    const float* Ap = A + (size_t)(row0 + tid) * K;
    int wr = tid >> 4;
    int wc = (tid & 15) * WC;

    for (int k0 = 0; k0 < K; k0 += BK) {
        // --- fill A tile (one row per thread, 16 k's), fused BN+ReLU ---
        float a16[16];
        *(float4*)&a16[0]  = *(const float4*)(Ap + k0 + 0);
        *(float4*)&a16[4]  = *(const float4*)(Ap + k0 + 4);
        *(float4*)&a16[8]  = *(const float4*)(Ap + k0 + 8);
        *(float4*)&a16[12] = *(const float4*)(Ap + k0 + 12);
        if (BNIN) {
#pragma unroll
            for (int u = 0; u < 16; u++)
                a16[u] = fmaxf(0.0f, fmaf(a16[u], sSc[k0+u], sSh[k0+u]));
        }
#pragma unroll
        for (int u = 0; u < 16; u++) As[u][tid] = a16[u];

        // --- fill W tile duplicated ---
        {
            const float* Wp = W + (size_t)(k0 + wr) * N + col0 + wc;
            float wv[WC];
            *(float4*)&wv[0] = *(const float4*)(Wp);
            if (WC == 8) *(float4*)&wv[4] = *(const float4*)(Wp + 4);
#pragma unroll
            for (int j = 0; j < WC; j++) Ws2[wr][wc + j] = make_float2(wv[j], wv[j]);
        }
        __syncthreads();

#pragma unroll
        for (int kk = 0; kk < BK; kk++) {
            ull a2[TM/2];
#pragma unroll
            for (int u = 0; u < TM/4; u++) {
                ulonglong2 t = *(const ulonglong2*)&As[kk][r0 + 4*u];
                a2[2*u] = t.x; a2[2*u+1] = t.y;
            }
            ull b2[TN];
#pragma unroll
            for (int u = 0; u < TN/2; u++) {
                ulonglong2 t = *(const ulonglong2*)&Ws2[kk][c0 + 2*u];
                b2[2*u] = t.x; b2[2*u+1] = t.y;
            }
#pragma unroll
            for (int j = 0; j < TN; j++)
#pragma unroll
                for (int i = 0; i < TM/2; i++)
                    ffma2(acc[i][j], a2[i], b2[j]);
        }
        __syncthreads();
    }

    // --- epilogue: bias, store C, column partial stats (deterministic) ---
    float bj[TN];
#pragma unroll
    for (int j = 0; j < TN; j++) bj[j] = __ldg(&bias[col0 + c0 + j]);

    float s[TN], qq[TN];
#pragma unroll
    for (int j = 0; j < TN; j++) { s[j] = 0.0f; qq[j] = 0.0f; }

#pragma unroll
    for (int i = 0; i < TM/2; i++) {
        float vlo[TN], vhi[TN];
#pragma unroll
        for (int j = 0; j < TN; j++) {
            float2 p = *(float2*)&acc[i][j];
            vlo[j] = p.x + bj[j];
            vhi[j] = p.y + bj[j];
        }
        float* Cr0 = C + (size_t)(row0 + r0 + 2*i)     * N + col0 + c0;
        float* Cr1 = C + (size_t)(row0 + r0 + 2*i + 1) * N + col0 + c0;
#pragma unroll
        for (int j = 0; j < TN; j += 4) {
            *(float4*)(Cr0 + j) = make_float4(vlo[j], vlo[j+1], vlo[j+2], vlo[j+3]);
            *(float4*)(Cr1 + j) = make_float4(vhi[j], vhi[j+1], vhi[j+2], vhi[j+3]);
        }
#pragma unroll
        for (int j = 0; j < TN; j++) {
            s[j] += vlo[j];  qq[j] = fmaf(vlo[j], vlo[j], qq[j]);
            s[j] += vhi[j];  qq[j] = fmaf(vhi[j], vhi[j], qq[j]);
        }
    }

    // reduce over the 16 trow groups in fixed order (sum pass, then sq pass)
#pragma unroll
    for (int j = 0; j < TN; j++) red[trow][c0 + j] = s[j];
    __syncthreads();
    if (trow == 0) {
#pragma unroll
        for (int j = 0; j < TN; j++) {
            float t = 0.0f;
            for (int u = 0; u < 16; u++) t += red[u][c0 + j];
            g_psum[blockIdx.y * N + col0 + c0 + j] = t;
        }
    }
    __syncthreads();
#pragma unroll
    for (int j = 0; j < TN; j++) red[trow][c0 + j] = qq[j];
    __syncthreads();
    if (trow == 0) {
#pragma unroll
        for (int j = 0; j < TN; j++) {
            float t = 0.0f;
            for (int u = 0; u < 16; u++) t += red[u][c0 + j];
            g_psq[blockIdx.y * N + col0 + c0 + j] = t;
        }
    }
}

// ---------------- BN finalize ----------------
__global__ void bnfin_kernel(const float* __restrict__ g, const float* __restrict__ be, int N) {
    int c = threadIdx.x;
    if (c >= N) return;
    double s = 0.0, q = 0.0;
    for (int rb = 0; rb < 128; rb++) { s += (double)g_psum[rb * N + c]; q += (double)g_psq[rb * N + c]; }
    double mean = s / (double)BB;
    double var  = q / (double)BB - mean * mean;
    float sc = g[c] * rsqrtf((float)var + 1e-5f);
    g_scale[c] = sc;
    g_shift[c] = be[c] - (float)mean * sc;
}

// ---------------- final layer 64 -> 2 (with fused BN5+ReLU) ----------------
__global__ void __launch_bounds__(256) layer6_kernel(
    const float* __restrict__ w6, const float* __restrict__ b6, float* __restrict__ out)
{
    __shared__ float w[128];
    __shared__ float sc[64], sh[64];
    __shared__ float bb2[2];
    int t = threadIdx.x;
    if (t < 128) w[t] = w6[t];
    if (t < 64) { sc[t] = g_scale[t]; sh[t] = g_shift[t]; }
    if (t < 2) bb2[t] = b6[t];
    __syncthreads();
    int r = blockIdx.x * blockDim.x + t;
    if (r >= BB) return;
    const float* x = g_X5 + (size_t)r * 64;
    float a0 = bb2[0], a1 = bb2[1];
#pragma unroll
    for (int k = 0; k < 64; k++) {
        float v = fmaxf(0.0f, fmaf(x[k], sc[k], sh[k]));
        a0 = fmaf(v, w[2*k],   a0);
        a1 = fmaf(v, w[2*k+1], a1);
    }
    out[2*r]   = a0;
    out[2*r+1] = a1;
}

// ---------------- launch ----------------
extern "C" void kernel_launch(void* const* d_in, const int* in_sizes, int n_in,
                              void* d_out, int out_size) {
    const float* pos = (const float*)d_in[0];
    const float* mc  = (const float*)d_in[1];
    const float* mv  = (const float*)d_in[2];
    const float* w1 = (const float*)d_in[3];  const float* b1 = (const float*)d_in[4];
    const float* w2 = (const float*)d_in[5];  const float* b2 = (const float*)d_in[6];
    const float* w3 = (const float*)d_in[7];  const float* b3 = (const float*)d_in[8];
    const float* w4 = (const float*)d_in[9];  const float* b4 = (const float*)d_in[10];
    const float* w5 = (const float*)d_in[11]; const float* b5 = (const float*)d_in[12];
    const float* w6 = (const float*)d_in[13]; const float* b6 = (const float*)d_in[14];
    const float* g1 = (const float*)d_in[15]; const float* be1 = (const float*)d_in[16];
    const float* g2 = (const float*)d_in[17]; const float* be2 = (const float*)d_in[18];
    const float* g3 = (const float*)d_in[19]; const float* be3 = (const float*)d_in[20];
    const float* g4 = (const float*)d_in[21]; const float* be4 = (const float*)d_in[22];
    const float* g5 = (const float*)d_in[23]; const float* be5 = (const float*)d_in[24];
    float* out = (float*)d_out;

    float *X0p, *X1, *X2, *X3, *X4, *X5, *W1p;
    cudaGetSymbolAddress((void**)&X0p, g_X0p);
    cudaGetSymbolAddress((void**)&X1,  g_X1);
    cudaGetSymbolAddress((void**)&X2,  g_X2);
    cudaGetSymbolAddress((void**)&X3,  g_X3);
    cudaGetSymbolAddress((void**)&X4,  g_X4);
    cudaGetSymbolAddress((void**)&X5,  g_X5);
    cudaGetSymbolAddress((void**)&W1p, g_W1p);

    // grid build + KNN feature assembly
    zero_cells_kernel<<<(NCELL + 255) / 256, 256>>>();
    count_kernel<<<(MM + 255) / 256, 256>>>(mc);
    scan_kernel<<<1, 256>>>();
    scatter_kernel<<<(MM + 255) / 256, 256>>>(mc);
    padw1_kernel<<<(80*128 + 255) / 256, 256>>>(w1);
    knn_kernel<<<BB / 256, 256>>>(pos, mc, mv, out + (size_t)BB * 2);

    // L1: 80(pad of 66) -> 128
    gemm2_kernel<128, 8, false><<<dim3(1, BB/256), 256>>>(X0p, W1p, b1, X1, 80, 128);
    bnfin_kernel<<<1, 128>>>(g1, be1, 128);

    // L2: 128 -> 256 (BN1+ReLU fused into A load)
    gemm2_kernel<128, 8, true><<<dim3(2, BB/256), 256>>>(X1, w2, b2, X2, 128, 256);
    bnfin_kernel<<<1, 256>>>(g2, be2, 256);

    // L3: 256 -> 512
    gemm2_kernel<128, 8, true><<<dim3(4, BB/256), 256>>>(X2, w3, b3, X3, 256, 512);
    bnfin_kernel<<<1, 512>>>(g3, be3, 512);

    // L4: 512 -> 128
    gemm2_kernel<128, 8, true><<<dim3(1, BB/256), 256>>>(X3, w4, b4, X4, 512, 128);
    bnfin_kernel<<<1, 128>>>(g4, be4, 128);

    // L5: 128 -> 64
    gemm2_kernel<64, 4, true><<<dim3(1, BB/256), 256>>>(X4, w5, b5, X5, 128, 64);
    bnfin_kernel<<<1, 64>>>(g5, be5, 64);

    // L6: 64 -> 2 (BN5+ReLU fused), writes x to out[0 : 2B]
    layer6_kernel<<<BB / 256, 256>>>(w6, b6, out);
}

// round 5
// speedup vs baseline: 1.1491x; 1.1491x over previous
#include <cuda_runtime.h>
#include <cuda_bf16.h>
#include <stdint.h>
#include <stddef.h>

#define BB 32768
#define MM 8192
#define GG 128
#define NCELL (GG*GG)

static __device__ __forceinline__ float f_inf() { return __int_as_float(0x7f800000); }

// ---------------- scratch (device globals; no allocation allowed) ----------------
__device__ float  g_X0p[BB*128];    // padded knn_feat (66 -> 128, zero pad)
__device__ float  g_X1[BB*128];
__device__ float  g_X2[BB*256];
__device__ float  g_X3[BB*512];
__device__ float  g_X4[BB*128];
__device__ float  g_X5[BB*64];
__device__ float  g_psum[256*512];  // per-128-rowblock column sums (max N=512)
__device__ float  g_psq [256*512];
__device__ float  g_scale[512];
__device__ float  g_shift[512];
__device__ int    g_cellCount[NCELL];
__device__ int    g_cellFill [NCELL];
__device__ int    g_cellStart[NCELL+1];
__device__ float4 g_packed[MM];     // (mx, my, mx^2+my^2, orig_idx)
__device__ float  g_W1p[128*128];   // zero-padded w1 (K 66->128)

// ---------------- PTX helpers (baseline PTX only: ldmatrix + mma.sync) ---------
static __device__ __forceinline__ uint32_t smem_u32(const void* p) {
    uint32_t a;
    asm("{ .reg .u64 t; cvta.to.shared.u64 t, %1; cvt.u32.u64 %0, t; }" : "=r"(a) : "l"(p));
    return a;
}
static __device__ __forceinline__ void ldsm4(uint32_t* r, uint32_t a) {
    asm volatile("ldmatrix.sync.aligned.m8n8.x4.shared.b16 {%0,%1,%2,%3}, [%4];"
        : "=r"(r[0]), "=r"(r[1]), "=r"(r[2]), "=r"(r[3]) : "r"(a));
}
static __device__ __forceinline__ void mma16816(float* d, const uint32_t* a,
                                                uint32_t b0, uint32_t b1) {
    asm volatile("mma.sync.aligned.m16n8k16.row.col.f32.bf16.bf16.f32 "
        "{%0,%1,%2,%3}, {%4,%5,%6,%7}, {%8,%9}, {%0,%1,%2,%3};"
        : "+f"(d[0]), "+f"(d[1]), "+f"(d[2]), "+f"(d[3])
        : "r"(a[0]), "r"(a[1]), "r"(a[2]), "r"(a[3]), "r"(b0), "r"(b1));
}
static __device__ __forceinline__ void bsplit(float a, __nv_bfloat16& h, __nv_bfloat16& l) {
    h = __float2bfloat16_rn(a);
    l = __float2bfloat16_rn(a - __bfloat162float(h));
}

// ---------------- grid build ----------------
__global__ void zero_cells_kernel() {
    int i = blockIdx.x*blockDim.x + threadIdx.x;
    if (i < NCELL) { g_cellCount[i] = 0; g_cellFill[i] = 0; }
}

__device__ __forceinline__ int cell_of(float v) {
    const float GMINF = -6.0f;
    const float INVH  = GG / 12.0f;
    int c = (int)floorf((v - GMINF) * INVH);
    return min(max(c, 0), GG-1);
}

__global__ void count_kernel(const float* __restrict__ mc) {
    int i = blockIdx.x*blockDim.x + threadIdx.x;
    if (i >= MM) return;
    int cx = cell_of(mc[2*i]);
    int cy = cell_of(mc[2*i+1]);
    atomicAdd(&g_cellCount[cy*GG + cx], 1);
}

__global__ void scan_kernel() {
    __shared__ int sums[256];
    int t = threadIdx.x;
    const int per = NCELL / 256;
    int base = t * per;
    int s = 0;
    for (int i = 0; i < per; i++) s += g_cellCount[base + i];
    sums[t] = s;
    __syncthreads();
    if (t == 0) {
        int acc = 0;
        for (int i = 0; i < 256; i++) { int v = sums[i]; sums[i] = acc; acc += v; }
    }
    __syncthreads();
    int off = sums[t];
    for (int i = 0; i < per; i++) { int v = g_cellCount[base + i]; g_cellStart[base + i] = off; off += v; }
    if (t == 255) g_cellStart[NCELL] = off;
}

__global__ void scatter_kernel(const float* __restrict__ mc) {
    int i = blockIdx.x*blockDim.x + threadIdx.x;
    if (i >= MM) return;
    float x = mc[2*i], y = mc[2*i+1];
    int cx = cell_of(x), cy = cell_of(y);
    int c = cy*GG + cx;
    int slot = g_cellStart[c] + atomicAdd(&g_cellFill[c], 1);
    float sm = __fadd_rn(__fmul_rn(x, x), __fmul_rn(y, y));
    g_packed[slot] = make_float4(x, y, sm, __int_as_float(i));
}

__global__ void padw1_kernel(const float* __restrict__ w1) {
    int i = blockIdx.x*blockDim.x + threadIdx.x;
    if (i >= 128*128) return;
    int row = i / 128, col = i % 128;
    g_W1p[i] = (row < 66) ? w1[row*128 + col] : 0.0f;
}

// ---------------- KNN ----------------
#define SCAN_RANGE(S_, E_)                                                        \
    for (int j_ = (S_); j_ < (E_); j_++) {                                        \
        float4 v_ = g_packed[j_];                                                 \
        float dot_ = __fmaf_rn(py, v_.y, __fmul_rn(px, v_.x));                    \
        float d2_  = __fmaf_rn(dot_, -2.0f, __fadd_rn(sp, v_.z));                 \
        int   mi_  = __float_as_int(v_.w);                                        \
        if (d2_ < key[15] || (d2_ == key[15] && mi_ < id[15])) {                  \
            float ck_ = d2_; int ci_ = mi_;                                       \
            _Pragma("unroll")                                                     \
            for (int t2_ = 0; t2_ < 16; t2_++) {                                  \
                bool sw_ = (ck_ < key[t2_]) || (ck_ == key[t2_] && ci_ < id[t2_]);\
                float tk_ = key[t2_]; int ti_ = id[t2_];                          \
                if (sw_) { key[t2_] = ck_; id[t2_] = ci_; ck_ = tk_; ci_ = ti_; } \
            }                                                                     \
        }                                                                         \
    }

__global__ void __launch_bounds__(256) knn_kernel(
    const float* __restrict__ pos, const float* __restrict__ mc,
    const float* __restrict__ mv, float* __restrict__ outKnn)
{
    const float GMINF = -6.0f;
    const float HCELL = 12.0f / GG;
    const float MARGIN = 1e-4f;
    int q = blockIdx.x*blockDim.x + threadIdx.x;
    if (q >= BB) return;
    float px = pos[2*q], py = pos[2*q+1];
    float sp = __fadd_rn(__fmul_rn(px, px), __fmul_rn(py, py));

    float key[16]; int id[16];
#pragma unroll
    for (int i = 0; i < 16; i++) { key[i] = f_inf(); id[i] = 0x7fffffff; }

    int cx = cell_of(px), cy = cell_of(py);

    for (int R = 0;; R++) {
        int xlo = cx - R, xhi = cx + R, ylo = cy - R, yhi = cy + R;
        int xl = max(xlo, 0), xh = min(xhi, GG-1);
        int yl = max(ylo, 0), yh = min(yhi, GG-1);
        for (int yy = yl; yy <= yh; yy++) {
            if (yy == ylo || yy == yhi) {
                int s = g_cellStart[yy*GG + xl];
                int e = g_cellStart[yy*GG + xh + 1];
                SCAN_RANGE(s, e)
            } else {
                if (xlo >= 0) {
                    int s = g_cellStart[yy*GG + xlo];
                    int e = g_cellStart[yy*GG + xlo + 1];
                    SCAN_RANGE(s, e)
                }
                if (xhi <= GG-1) {
                    int s = g_cellStart[yy*GG + xhi];
                    int e = g_cellStart[yy*GG + xhi + 1];
                    SCAN_RANGE(s, e)
                }
            }
        }
        bool full = (xlo <= 0 && ylo <= 0 && xhi >= GG-1 && yhi >= GG-1);
        float x0 = GMINF + xlo * HCELL, x1 = GMINF + (xhi + 1) * HCELL;
        float y0 = GMINF + ylo * HCELL, y1 = GMINF + (yhi + 1) * HCELL;
        float db = fminf(fminf(px - x0, x1 - px), fminf(py - y0, y1 - py));
        if (full || (db > 0.0f && db*db > key[15] + MARGIN)) break;
    }

    float* o  = outKnn + (size_t)q * 66;
    float* xo = g_X0p  + (size_t)q * 128;
    o[0] = px; o[1] = py; xo[0] = px; xo[1] = py;
#pragma unroll
    for (int n = 0; n < 16; n++) {
        int mi = id[n];
        float ax = mc[2*mi], ay = mc[2*mi+1];
        float vx = mv[2*mi], vy = mv[2*mi+1];
        o[2+4*n] = ax; o[3+4*n] = ay; o[4+4*n] = vx; o[5+4*n] = vy;
        xo[2+4*n] = ax; xo[3+4*n] = ay; xo[4+4*n] = vx; xo[5+4*n] = vy;
    }
    for (int c = 66; c < 128; c += 2) { xo[c] = 0.0f; xo[c+1] = 0.0f; }
}

// ---------------- HMMA bf16x3 GEMM, BN+ReLU fused on A, fused col stats -------
// C[B,N] = act(A)[B,K] @ W[K,N] + bias, fp32 accum in registers (mma.sync).
// A,W split bf16 hi/lo; 3-term: Ah*Wh + Ah*Wl + Al*Wh.
// CTA tile 128 x BNT, 8 warps (4 x 2), warp tile 32 x (BNT/2), K stages of 64.
template<int BNT, bool BNIN>
__global__ void __launch_bounds__(256, 1)
tcgemm_kernel(const float* __restrict__ A, const float* __restrict__ W,
              const float* __restrict__ bias, float* __restrict__ C,
              int K, int N)
{
    extern __shared__ char sm[];
    constexpr int NW  = BNT / 2;       // cols per warp
    constexpr int NB8 = NW / 8;        // n8 blocks per warp
    constexpr int NG  = NW / 16;       // n16 ldmatrix groups per warp
    constexpr int SS  = BNT + 4;       // stage stride (floats)
    constexpr int SM_BIAS = 64;
    constexpr int SM_SC   = 1024;
    constexpr int SM_SH   = 3072;
    constexpr int TIL = 6144;
    constexpr int AHI = TIL;                 // [128][72] bf16 = 18432 B
    constexpr int ALO = AHI + 128*144;
    constexpr int BHI = ALO + 128*144;       // [BNT][72] bf16
    constexpr int BLO = BHI + BNT*144;
    constexpr int TEND = BLO + BNT*144;
    constexpr int STGO = TIL;                // float [128][SS], aliases tiles
    constexpr int RED  = TEND;               // 2048 B

    uint32_t sbase = smem_u32(sm);
    int tid = threadIdx.x;
    int wid = tid >> 5, lane = tid & 31;
    int wm = wid & 3, wn = wid >> 2;
    int row0 = blockIdx.y * 128;
    int col0 = blockIdx.x * BNT;

    float* sBias = (float*)(sm + SM_BIAS);
    float* sSc   = (float*)(sm + SM_SC);
    float* sSh   = (float*)(sm + SM_SH);
    for (int i = tid; i < BNT; i += 256) sBias[i] = bias[col0 + i];
    if (BNIN) {
        for (int i = tid; i < K; i += 256) { sSc[i] = g_scale[i]; sSh[i] = g_shift[i]; }
    }
    __syncthreads();

    float d[2][NB8][4];
#pragma unroll
    for (int mt = 0; mt < 2; mt++)
#pragma unroll
        for (int nb = 0; nb < NB8; nb++)
#pragma unroll
            for (int j = 0; j < 4; j++) d[mt][nb][j] = 0.0f;

    const int nst = K / 64;
    for (int s = 0; s < nst; s++) {
        int k0 = s * 64;
        // --- fill A tile: 128 rows x 64 k ---
#pragma unroll
        for (int it = 0; it < 8; it++) {
            int w = tid + it * 256;
            int m = w >> 4;
            int kc = (w & 15) * 4;
            float4 a = *(const float4*)(A + (size_t)(row0 + m) * K + k0 + kc);
            float av[4] = {a.x, a.y, a.z, a.w};
            if (BNIN) {
#pragma unroll
                for (int j = 0; j < 4; j++)
                    av[j] = fmaxf(0.0f, fmaf(av[j], sSc[k0+kc+j], sSh[k0+kc+j]));
            }
            __nv_bfloat16 h[4], l[4];
#pragma unroll
            for (int j = 0; j < 4; j++) bsplit(av[j], h[j], l[j]);
            uint32_t bo = (uint32_t)(m * 72 + kc) * 2;
            *(__nv_bfloat162*)(sm + AHI + bo)     = __halves2bfloat162(h[0], h[1]);
            *(__nv_bfloat162*)(sm + AHI + bo + 4) = __halves2bfloat162(h[2], h[3]);
            *(__nv_bfloat162*)(sm + ALO + bo)     = __halves2bfloat162(l[0], l[1]);
            *(__nv_bfloat162*)(sm + ALO + bo + 4) = __halves2bfloat162(l[2], l[3]);
        }
        // --- fill B tile: Wt[n][k], BNT x 64 ---
        for (int w = tid; w < 32 * (BNT/4); w += 256) {
            int kp = w / (BNT/4);
            int n0 = (w % (BNT/4)) * 4;
            int k  = kp * 2;
            const float* wp0 = W + (size_t)(k0 + k) * N + col0 + n0;
            float4 r0 = *(const float4*)wp0;
            float4 r1 = *(const float4*)(wp0 + N);
            float v0[4] = {r0.x, r0.y, r0.z, r0.w};
            float v1[4] = {r1.x, r1.y, r1.z, r1.w};
#pragma unroll
            for (int j = 0; j < 4; j++) {
                __nv_bfloat16 h0, l0, h1, l1;
                bsplit(v0[j], h0, l0);
                bsplit(v1[j], h1, l1);
                uint32_t bo = (uint32_t)((n0 + j) * 72 + k) * 2;
                *(__nv_bfloat162*)(sm + BHI + bo) = __halves2bfloat162(h0, h1);
                *(__nv_bfloat162*)(sm + BLO + bo) = __halves2bfloat162(l0, l1);
            }
        }
        __syncthreads();

        // --- compute: 4 k16 steps ---
        int lr = lane & 15, lc = lane >> 4;
#pragma unroll
        for (int kst = 0; kst < 4; kst++) {
            uint32_t koff = (uint32_t)(kst * 16 + lc * 8) * 2;
            uint32_t bh[NG][4], bl[NG][4];
#pragma unroll
            for (int g = 0; g < NG; g++) {
                uint32_t bo = (uint32_t)((wn*NW + g*16 + lr) * 72) * 2 + koff;
                ldsm4(bh[g], sbase + BHI + bo);
                ldsm4(bl[g], sbase + BLO + bo);
            }
#pragma unroll
            for (int mt = 0; mt < 2; mt++) {
                uint32_t ao = (uint32_t)((wm*32 + mt*16 + lr) * 72) * 2 + koff;
                uint32_t ah[4], al[4];
                ldsm4(ah, sbase + AHI + ao);
                ldsm4(al, sbase + ALO + ao);
#pragma unroll
                for (int g = 0; g < NG; g++) {
                    mma16816(d[mt][2*g],   ah, bh[g][0], bh[g][2]);
                    mma16816(d[mt][2*g],   ah, bl[g][0], bl[g][2]);
                    mma16816(d[mt][2*g],   al, bh[g][0], bh[g][2]);
                    mma16816(d[mt][2*g+1], ah, bh[g][1], bh[g][3]);
                    mma16816(d[mt][2*g+1], ah, bl[g][1], bl[g][3]);
                    mma16816(d[mt][2*g+1], al, bh[g][1], bh[g][3]);
                }
            }
        }
        __syncthreads();
    }

    // --- epilogue: stage (bias added) -> coalesced store + deterministic stats ---
    float* stg = (float*)(sm + STGO);
    float* red = (float*)(sm + RED);
#pragma unroll
    for (int mt = 0; mt < 2; mt++)
#pragma unroll
        for (int nb = 0; nb < NB8; nb++) {
            int col = wn*NW + nb*8 + 2*(lane & 3);
            int row = wm*32 + mt*16 + (lane >> 2);
            float b0 = sBias[col], b1 = sBias[col+1];
            stg[row*SS + col]       = d[mt][nb][0] + b0;
            stg[row*SS + col + 1]   = d[mt][nb][1] + b1;
            stg[(row+8)*SS + col]   = d[mt][nb][2] + b0;
            stg[(row+8)*SS + col+1] = d[mt][nb][3] + b1;
        }
    __syncthreads();

    for (int idx = tid; idx < 128 * (BNT/4); idx += 256) {
        int m  = idx / (BNT/4);
        int j4 = (idx % (BNT/4)) * 4;
        float4 v;
        v.x = stg[m*SS + j4 + 0];
        v.y = stg[m*SS + j4 + 1];
        v.z = stg[m*SS + j4 + 2];
        v.w = stg[m*SS + j4 + 3];
        *(float4*)(C + (size_t)(row0 + m) * N + col0 + j4) = v;
    }

#pragma unroll
    for (int c = 0; c < BNT/32; c++) {
        int j = tid & 31, seg = tid >> 5;
        float s2 = 0.0f, q2 = 0.0f;
        for (int r2 = 0; r2 < 16; r2++) {
            float v = stg[(seg*16 + r2) * SS + c*32 + j];
            s2 += v;
            q2 = fmaf(v, v, q2);
        }
        red[seg*32 + j] = s2;
        red[256 + seg*32 + j] = q2;
        __syncthreads();
        if (tid < 32) {
            float s = 0.0f, q = 0.0f;
            for (int u = 0; u < 8; u++) { s += red[u*32 + tid]; q += red[256 + u*32 + tid]; }
            g_psum[blockIdx.y * N + col0 + c*32 + tid] = s;
            g_psq [blockIdx.y * N + col0 + c*32 + tid] = q;
        }
        __syncthreads();
    }
}

// ---------------- BN finalize ----------------
__global__ void bnfin_kernel(const float* __restrict__ g, const float* __restrict__ be, int N) {
    int c = threadIdx.x;
    if (c >= N) return;
    double s = 0.0, q = 0.0;
    for (int rb = 0; rb < 256; rb++) { s += (double)g_psum[rb * N + c]; q += (double)g_psq[rb * N + c]; }
    double mean = s / (double)BB;
    double var  = q / (double)BB - mean * mean;
    float sc = g[c] * rsqrtf((float)var + 1e-5f);
    g_scale[c] = sc;
    g_shift[c] = be[c] - (float)mean * sc;
}

// ---------------- final layer 64 -> 2 (with fused BN5+ReLU) ----------------
__global__ void __launch_bounds__(256) layer6_kernel(
    const float* __restrict__ w6, const float* __restrict__ b6, float* __restrict__ out)
{
    __shared__ float w[128];
    __shared__ float sc[64], sh[64];
    __shared__ float bb2[2];
    int t = threadIdx.x;
    if (t < 128) w[t] = w6[t];
    if (t < 64) { sc[t] = g_scale[t]; sh[t] = g_shift[t]; }
    if (t < 2) bb2[t] = b6[t];
    __syncthreads();
    int r = blockIdx.x * blockDim.x + t;
    if (r >= BB) return;
    const float* x = g_X5 + (size_t)r * 64;
    float a0 = bb2[0], a1 = bb2[1];
#pragma unroll
    for (int k = 0; k < 64; k++) {
        float v = fmaxf(0.0f, fmaf(x[k], sc[k], sh[k]));
        a0 = fmaf(v, w[2*k],   a0);
        a1 = fmaf(v, w[2*k+1], a1);
    }
    out[2*r]   = a0;
    out[2*r+1] = a1;
}

// ---------------- launch ----------------
extern "C" void kernel_launch(void* const* d_in, const int* in_sizes, int n_in,
                              void* d_out, int out_size) {
    const float* pos = (const float*)d_in[0];
    const float* mc  = (const float*)d_in[1];
    const float* mv  = (const float*)d_in[2];
    const float* w1 = (const float*)d_in[3];  const float* b1 = (const float*)d_in[4];
    const float* w2 = (const float*)d_in[5];  const float* b2 = (const float*)d_in[6];
    const float* w3 = (const float*)d_in[7];  const float* b3 = (const float*)d_in[8];
    const float* w4 = (const float*)d_in[9];  const float* b4 = (const float*)d_in[10];
    const float* w5 = (const float*)d_in[11]; const float* b5 = (const float*)d_in[12];
    const float* w6 = (const float*)d_in[13]; const float* b6 = (const float*)d_in[14];
    const float* g1 = (const float*)d_in[15]; const float* be1 = (const float*)d_in[16];
    const float* g2 = (const float*)d_in[17]; const float* be2 = (const float*)d_in[18];
    const float* g3 = (const float*)d_in[19]; const float* be3 = (const float*)d_in[20];
    const float* g4 = (const float*)d_in[21]; const float* be4 = (const float*)d_in[22];
    const float* g5 = (const float*)d_in[23]; const float* be5 = (const float*)d_in[24];
    float* out = (float*)d_out;

    float *X0p, *X1, *X2, *X3, *X4, *X5, *W1p;
    cudaGetSymbolAddress((void**)&X0p, g_X0p);
    cudaGetSymbolAddress((void**)&X1,  g_X1);
    cudaGetSymbolAddress((void**)&X2,  g_X2);
    cudaGetSymbolAddress((void**)&X3,  g_X3);
    cudaGetSymbolAddress((void**)&X4,  g_X4);
    cudaGetSymbolAddress((void**)&X5,  g_X5);
    cudaGetSymbolAddress((void**)&W1p, g_W1p);

    // smem: tiles end + 2KB red
    const int SMEM128 = 6144 + 2*128*144 + 2*128*144 + 2048;  // 81920
    const int SMEM64  = 6144 + 2*128*144 + 2*64*144  + 2048;  // 63488
    cudaFuncSetAttribute(tcgemm_kernel<128,false>,
                         cudaFuncAttributeMaxDynamicSharedMemorySize, SMEM128);
    cudaFuncSetAttribute(tcgemm_kernel<128,true>,
                         cudaFuncAttributeMaxDynamicSharedMemorySize, SMEM128);
    cudaFuncSetAttribute(tcgemm_kernel<64,true>,
                         cudaFuncAttributeMaxDynamicSharedMemorySize, SMEM64);

    // grid build + KNN feature assembly
    zero_cells_kernel<<<(NCELL + 255) / 256, 256>>>();
    count_kernel<<<(MM + 255) / 256, 256>>>(mc);
    scan_kernel<<<1, 256>>>();
    scatter_kernel<<<(MM + 255) / 256, 256>>>(mc);
    padw1_kernel<<<(128*128 + 255) / 256, 256>>>(w1);
    knn_kernel<<<BB / 256, 256>>>(pos, mc, mv, out + (size_t)BB * 2);

    // L1: 128(pad of 66) -> 128
    tcgemm_kernel<128,false><<<dim3(1, BB/128), 256, SMEM128>>>(X0p, W1p, b1, X1, 128, 128);
    bnfin_kernel<<<1, 128>>>(g1, be1, 128);

    // L2: 128 -> 256
    tcgemm_kernel<128,true><<<dim3(2, BB/128), 256, SMEM128>>>(X1, w2, b2, X2, 128, 256);
    bnfin_kernel<<<1, 256>>>(g2, be2, 256);

    // L3: 256 -> 512
    tcgemm_kernel<128,true><<<dim3(4, BB/128), 256, SMEM128>>>(X2, w3, b3, X3, 256, 512);
    bnfin_kernel<<<1, 512>>>(g3, be3, 512);

    // L4: 512 -> 128
    tcgemm_kernel<128,true><<<dim3(1, BB/128), 256, SMEM128>>>(X3, w4, b4, X4, 512, 128);
    bnfin_kernel<<<1, 128>>>(g4, be4, 128);

    // L5: 128 -> 64
    tcgemm_kernel<64,true><<<dim3(1, BB/128), 256, SMEM64>>>(X4, w5, b5, X5, 128, 64);
    bnfin_kernel<<<1, 64>>>(g5, be5, 64);

    // L6: 64 -> 2 (BN5+ReLU fused), writes x to out[0 : 2B]
    layer6_kernel<<<BB / 256, 256>>>(w6, b6, out);
}

// round 6
// speedup vs baseline: 1.1611x; 1.0104x over previous
#include <cuda_runtime.h>
#include <cuda_bf16.h>
#include <stdint.h>
#include <stddef.h>

#define BB 32768
#define MM 8192
#define GG 128
#define NCELL (GG*GG)

static __device__ __forceinline__ float f_inf() { return __int_as_float(0x7f800000); }

// ---------------- scratch (device globals; no allocation allowed) ----------------
__device__ float  g_X0p[BB*128];    // padded knn_feat (66 -> 128, zero pad)
__device__ float  g_X1[BB*128];
__device__ float  g_X2[BB*256];
__device__ float  g_X3[BB*512];
__device__ float  g_X4[BB*128];
__device__ float  g_X5[BB*64];
__device__ float  g_psum[256*512];
__device__ float  g_psq [256*512];
__device__ float  g_scale[512];
__device__ float  g_shift[512];
__device__ int    g_cellCount[NCELL];
__device__ int    g_cellFill [NCELL];
__device__ int    g_cellStart[NCELL+1];
__device__ int    g_qCount[NCELL];
__device__ int    g_qFill [NCELL];
__device__ int    g_qStart[NCELL+1];
__device__ int    g_qIdx[BB];
__device__ float4 g_packed[MM];     // (mx, my, mx^2+my^2, orig_idx)
__device__ float  g_W1p[128*128];   // zero-padded w1 (K 66->128)

// ---------------- PTX helpers (baseline PTX only: ldmatrix + mma.sync) ---------
static __device__ __forceinline__ uint32_t smem_u32(const void* p) {
    uint32_t a;
    asm("{ .reg .u64 t; cvta.to.shared.u64 t, %1; cvt.u32.u64 %0, t; }" : "=r"(a) : "l"(p));
    return a;
}
static __device__ __forceinline__ void ldsm4(uint32_t* r, uint32_t a) {
    asm volatile("ldmatrix.sync.aligned.m8n8.x4.shared.b16 {%0,%1,%2,%3}, [%4];"
        : "=r"(r[0]), "=r"(r[1]), "=r"(r[2]), "=r"(r[3]) : "r"(a));
}
static __device__ __forceinline__ void mma16816(float* d, const uint32_t* a,
                                                uint32_t b0, uint32_t b1) {
    asm volatile("mma.sync.aligned.m16n8k16.row.col.f32.bf16.bf16.f32 "
        "{%0,%1,%2,%3}, {%4,%5,%6,%7}, {%8,%9}, {%0,%1,%2,%3};"
        : "+f"(d[0]), "+f"(d[1]), "+f"(d[2]), "+f"(d[3])
        : "r"(a[0]), "r"(a[1]), "r"(a[2]), "r"(a[3]), "r"(b0), "r"(b1));
}
static __device__ __forceinline__ void bsplit(float a, __nv_bfloat16& h, __nv_bfloat16& l) {
    h = __float2bfloat16_rn(a);
    l = __float2bfloat16_rn(a - __bfloat162float(h));
}

// ---------------- grid build ----------------
__global__ void zero_cells_kernel() {
    int i = blockIdx.x*blockDim.x + threadIdx.x;
    if (i < NCELL) { g_cellCount[i] = 0; g_cellFill[i] = 0; g_qCount[i] = 0; g_qFill[i] = 0; }
}

__device__ __forceinline__ int cell_of(float v) {
    const float GMINF = -6.0f;
    const float INVH  = GG / 12.0f;
    int c = (int)floorf((v - GMINF) * INVH);
    return min(max(c, 0), GG-1);
}

__global__ void count_kernel(const float* __restrict__ mc) {
    int i = blockIdx.x*blockDim.x + threadIdx.x;
    if (i >= MM) return;
    int cx = cell_of(mc[2*i]);
    int cy = cell_of(mc[2*i+1]);
    atomicAdd(&g_cellCount[cy*GG + cx], 1);
}

__global__ void qcount_kernel(const float* __restrict__ pos) {
    int i = blockIdx.x*blockDim.x + threadIdx.x;
    if (i >= BB) return;
    int cx = cell_of(pos[2*i]);
    int cy = cell_of(pos[2*i+1]);
    atomicAdd(&g_qCount[cy*GG + cx], 1);
}

__global__ void scan_generic_kernel(const int* __restrict__ cnt, int* __restrict__ start) {
    __shared__ int sums[256];
    int t = threadIdx.x;
    const int per = NCELL / 256;
    int base = t * per;
    int s = 0;
    for (int i = 0; i < per; i++) s += cnt[base + i];
    sums[t] = s;
    __syncthreads();
    if (t == 0) {
        int acc = 0;
        for (int i = 0; i < 256; i++) { int v = sums[i]; sums[i] = acc; acc += v; }
    }
    __syncthreads();
    int off = sums[t];
    for (int i = 0; i < per; i++) { int v = cnt[base + i]; start[base + i] = off; off += v; }
    if (t == 255) start[NCELL] = off;
}

__global__ void scatter_kernel(const float* __restrict__ mc) {
    int i = blockIdx.x*blockDim.x + threadIdx.x;
    if (i >= MM) return;
    float x = mc[2*i], y = mc[2*i+1];
    int cx = cell_of(x), cy = cell_of(y);
    int c = cy*GG + cx;
    int slot = g_cellStart[c] + atomicAdd(&g_cellFill[c], 1);
    float sm = __fadd_rn(__fmul_rn(x, x), __fmul_rn(y, y));
    g_packed[slot] = make_float4(x, y, sm, __int_as_float(i));
}

__global__ void qscatter_kernel(const float* __restrict__ pos) {
    int i = blockIdx.x*blockDim.x + threadIdx.x;
    if (i >= BB) return;
    int cx = cell_of(pos[2*i]);
    int cy = cell_of(pos[2*i+1]);
    int c = cy*GG + cx;
    int slot = g_qStart[c] + atomicAdd(&g_qFill[c], 1);
    g_qIdx[slot] = i;
}

__global__ void padw1_kernel(const float* __restrict__ w1) {
    int i = blockIdx.x*blockDim.x + threadIdx.x;
    if (i >= 128*128) return;
    int row = i / 128, col = i % 128;
    g_W1p[i] = (row < 66) ? w1[row*128 + col] : 0.0f;
}

// ---------------- KNN (queries processed in cell-sorted order) ----------------
#define SCAN_RANGE(S_, E_)                                                        \
    for (int j_ = (S_); j_ < (E_); j_++) {                                        \
        float4 v_ = g_packed[j_];                                                 \
        float dot_ = __fmaf_rn(py, v_.y, __fmul_rn(px, v_.x));                    \
        float d2_  = __fmaf_rn(dot_, -2.0f, __fadd_rn(sp, v_.z));                 \
        int   mi_  = __float_as_int(v_.w);                                        \
        if (d2_ < key[15] || (d2_ == key[15] && mi_ < id[15])) {                  \
            float ck_ = d2_; int ci_ = mi_;                                       \
            _Pragma("unroll")                                                     \
            for (int t2_ = 0; t2_ < 16; t2_++) {                                  \
                bool sw_ = (ck_ < key[t2_]) || (ck_ == key[t2_] && ci_ < id[t2_]);\
                float tk_ = key[t2_]; int ti_ = id[t2_];                          \
                if (sw_) { key[t2_] = ck_; id[t2_] = ci_; ck_ = tk_; ci_ = ti_; } \
            }                                                                     \
        }                                                                         \
    }

__global__ void __launch_bounds__(256) knn_kernel(
    const float* __restrict__ pos, const float* __restrict__ mc,
    const float* __restrict__ mv, float* __restrict__ outKnn)
{
    const float GMINF = -6.0f;
    const float HCELL = 12.0f / GG;
    const float MARGIN = 1e-4f;
    int slot = blockIdx.x*blockDim.x + threadIdx.x;
    if (slot >= BB) return;
    int q = g_qIdx[slot];
    float px = pos[2*q], py = pos[2*q+1];
    float sp = __fadd_rn(__fmul_rn(px, px), __fmul_rn(py, py));

    float key[16]; int id[16];
#pragma unroll
    for (int i = 0; i < 16; i++) { key[i] = f_inf(); id[i] = 0x7fffffff; }

    int cx = cell_of(px), cy = cell_of(py);

    for (int R = 0;; R++) {
        int xlo = cx - R, xhi = cx + R, ylo = cy - R, yhi = cy + R;
        int xl = max(xlo, 0), xh = min(xhi, GG-1);
        int yl = max(ylo, 0), yh = min(yhi, GG-1);
        for (int yy = yl; yy <= yh; yy++) {
            if (yy == ylo || yy == yhi) {
                int s = g_cellStart[yy*GG + xl];
                int e = g_cellStart[yy*GG + xh + 1];
                SCAN_RANGE(s, e)
            } else {
                if (xlo >= 0) {
                    int s = g_cellStart[yy*GG + xlo];
                    int e = g_cellStart[yy*GG + xlo + 1];
                    SCAN_RANGE(s, e)
                }
                if (xhi <= GG-1) {
                    int s = g_cellStart[yy*GG + xhi];
                    int e = g_cellStart[yy*GG + xhi + 1];
                    SCAN_RANGE(s, e)
                }
            }
        }
        bool full = (xlo <= 0 && ylo <= 0 && xhi >= GG-1 && yhi >= GG-1);
        float x0 = GMINF + xlo * HCELL, x1 = GMINF + (xhi + 1) * HCELL;
        float y0 = GMINF + ylo * HCELL, y1 = GMINF + (yhi + 1) * HCELL;
        float db = fminf(fminf(px - x0, x1 - px), fminf(py - y0, y1 - py));
        if (full || (db > 0.0f && db*db > key[15] + MARGIN)) break;
    }

    float* o  = outKnn + (size_t)q * 66;
    float* xo = g_X0p  + (size_t)q * 128;
    o[0] = px; o[1] = py; xo[0] = px; xo[1] = py;
#pragma unroll
    for (int n = 0; n < 16; n++) {
        int mi = id[n];
        float ax = mc[2*mi], ay = mc[2*mi+1];
        float vx = mv[2*mi], vy = mv[2*mi+1];
        o[2+4*n] = ax; o[3+4*n] = ay; o[4+4*n] = vx; o[5+4*n] = vy;
        xo[2+4*n] = ax; xo[3+4*n] = ay; xo[4+4*n] = vx; xo[5+4*n] = vy;
    }
    for (int c = 66; c < 128; c += 2) { xo[c] = 0.0f; xo[c+1] = 0.0f; }
}

// ---------------- HMMA bf16x3 GEMM, BN+ReLU fused on A, fused col stats -------
template<int BNT, bool BNIN>
__global__ void __launch_bounds__(256, 1)
tcgemm_kernel(const float* __restrict__ A, const float* __restrict__ W,
              const float* __restrict__ bias, float* __restrict__ C,
              int K, int N)
{
    extern __shared__ char sm[];
    constexpr int NW  = BNT / 2;
    constexpr int NB8 = NW / 8;
    constexpr int NG  = NW / 16;
    constexpr int SS  = BNT + 4;
    constexpr int SM_BIAS = 64;
    constexpr int SM_SC   = 1024;
    constexpr int SM_SH   = 3072;
    constexpr int TIL = 6144;
    constexpr int AHI = TIL;
    constexpr int ALO = AHI + 128*144;
    constexpr int BHI = ALO + 128*144;
    constexpr int BLO = BHI + BNT*144;
    constexpr int TEND = BLO + BNT*144;
    constexpr int STGO = TIL;
    constexpr int RED  = TEND;

    uint32_t sbase = smem_u32(sm);
    int tid = threadIdx.x;
    int wid = tid >> 5, lane = tid & 31;
    int wm = wid & 3, wn = wid >> 2;
    int row0 = blockIdx.y * 128;
    int col0 = blockIdx.x * BNT;

    float* sBias = (float*)(sm + SM_BIAS);
    float* sSc   = (float*)(sm + SM_SC);
    float* sSh   = (float*)(sm + SM_SH);
    for (int i = tid; i < BNT; i += 256) sBias[i] = bias[col0 + i];
    if (BNIN) {
        for (int i = tid; i < K; i += 256) { sSc[i] = g_scale[i]; sSh[i] = g_shift[i]; }
    }
    __syncthreads();

    float d[2][NB8][4];
#pragma unroll
    for (int mt = 0; mt < 2; mt++)
#pragma unroll
        for (int nb = 0; nb < NB8; nb++)
#pragma unroll
            for (int j = 0; j < 4; j++) d[mt][nb][j] = 0.0f;

    const int nst = K / 64;
    for (int s = 0; s < nst; s++) {
        int k0 = s * 64;
#pragma unroll
        for (int it = 0; it < 8; it++) {
            int w = tid + it * 256;
            int m = w >> 4;
            int kc = (w & 15) * 4;
            float4 a = *(const float4*)(A + (size_t)(row0 + m) * K + k0 + kc);
            float av[4] = {a.x, a.y, a.z, a.w};
            if (BNIN) {
#pragma unroll
                for (int j = 0; j < 4; j++)
                    av[j] = fmaxf(0.0f, fmaf(av[j], sSc[k0+kc+j], sSh[k0+kc+j]));
            }
            __nv_bfloat16 h[4], l[4];
#pragma unroll
            for (int j = 0; j < 4; j++) bsplit(av[j], h[j], l[j]);
            uint32_t bo = (uint32_t)(m * 72 + kc) * 2;
            *(__nv_bfloat162*)(sm + AHI + bo)     = __halves2bfloat162(h[0], h[1]);
            *(__nv_bfloat162*)(sm + AHI + bo + 4) = __halves2bfloat162(h[2], h[3]);
            *(__nv_bfloat162*)(sm + ALO + bo)     = __halves2bfloat162(l[0], l[1]);
            *(__nv_bfloat162*)(sm + ALO + bo + 4) = __halves2bfloat162(l[2], l[3]);
        }
        for (int w = tid; w < 32 * (BNT/4); w += 256) {
            int kp = w / (BNT/4);
            int n0 = (w % (BNT/4)) * 4;
            int k  = kp * 2;
            const float* wp0 = W + (size_t)(k0 + k) * N + col0 + n0;
            float4 r0 = *(const float4*)wp0;
            float4 r1 = *(const float4*)(wp0 + N);
            float v0[4] = {r0.x, r0.y, r0.z, r0.w};
            float v1[4] = {r1.x, r1.y, r1.z, r1.w};
#pragma unroll
            for (int j = 0; j < 4; j++) {
                __nv_bfloat16 h0, l0, h1, l1;
                bsplit(v0[j], h0, l0);
                bsplit(v1[j], h1, l1);
                uint32_t bo = (uint32_t)((n0 + j) * 72 + k) * 2;
                *(__nv_bfloat162*)(sm + BHI + bo) = __halves2bfloat162(h0, h1);
                *(__nv_bfloat162*)(sm + BLO + bo) = __halves2bfloat162(l0, l1);
            }
        }
        __syncthreads();

        int lr = lane & 15, lc = lane >> 4;
#pragma unroll
        for (int kst = 0; kst < 4; kst++) {
            uint32_t koff = (uint32_t)(kst * 16 + lc * 8) * 2;
            uint32_t bh[NG][4], bl[NG][4];
#pragma unroll
            for (int g = 0; g < NG; g++) {
                uint32_t bo = (uint32_t)((wn*NW + g*16 + lr) * 72) * 2 + koff;
                ldsm4(bh[g], sbase + BHI + bo);
                ldsm4(bl[g], sbase + BLO + bo);
            }
#pragma unroll
            for (int mt = 0; mt < 2; mt++) {
                uint32_t ao = (uint32_t)((wm*32 + mt*16 + lr) * 72) * 2 + koff;
                uint32_t ah[4], al[4];
                ldsm4(ah, sbase + AHI + ao);
                ldsm4(al, sbase + ALO + ao);
#pragma unroll
                for (int g = 0; g < NG; g++) {
                    mma16816(d[mt][2*g],   ah, bh[g][0], bh[g][2]);
                    mma16816(d[mt][2*g],   ah, bl[g][0], bl[g][2]);
                    mma16816(d[mt][2*g],   al, bh[g][0], bh[g][2]);
                    mma16816(d[mt][2*g+1], ah, bh[g][1], bh[g][3]);
                    mma16816(d[mt][2*g+1], ah, bl[g][1], bl[g][3]);
                    mma16816(d[mt][2*g+1], al, bh[g][1], bh[g][3]);
                }
            }
        }
        __syncthreads();
    }

    float* stg = (float*)(sm + STGO);
    float* red = (float*)(sm + RED);
#pragma unroll
    for (int mt = 0; mt < 2; mt++)
#pragma unroll
        for (int nb = 0; nb < NB8; nb++) {
            int col = wn*NW + nb*8 + 2*(lane & 3);
            int row = wm*32 + mt*16 + (lane >> 2);
            float b0 = sBias[col], b1 = sBias[col+1];
            stg[row*SS + col]       = d[mt][nb][0] + b0;
            stg[row*SS + col + 1]   = d[mt][nb][1] + b1;
            stg[(row+8)*SS + col]   = d[mt][nb][2] + b0;
            stg[(row+8)*SS + col+1] = d[mt][nb][3] + b1;
        }
    __syncthreads();

    for (int idx = tid; idx < 128 * (BNT/4); idx += 256) {
        int m  = idx / (BNT/4);
        int j4 = (idx % (BNT/4)) * 4;
        float4 v;
        v.x = stg[m*SS + j4 + 0];
        v.y = stg[m*SS + j4 + 1];
        v.z = stg[m*SS + j4 + 2];
        v.w = stg[m*SS + j4 + 3];
        *(float4*)(C + (size_t)(row0 + m) * N + col0 + j4) = v;
    }

#pragma unroll
    for (int c = 0; c < BNT/32; c++) {
        int j = tid & 31, seg = tid >> 5;
        float s2 = 0.0f, q2 = 0.0f;
        for (int r2 = 0; r2 < 16; r2++) {
            float v = stg[(seg*16 + r2) * SS + c*32 + j];
            s2 += v;
            q2 = fmaf(v, v, q2);
        }
        red[seg*32 + j] = s2;
        red[256 + seg*32 + j] = q2;
        __syncthreads();
        if (tid < 32) {
            float s = 0.0f, q = 0.0f;
            for (int u = 0; u < 8; u++) { s += red[u*32 + tid]; q += red[256 + u*32 + tid]; }
            g_psum[blockIdx.y * N + col0 + c*32 + tid] = s;
            g_psq [blockIdx.y * N + col0 + c*32 + tid] = q;
        }
        __syncthreads();
    }
}

// ---------------- BN finalize ----------------
__global__ void bnfin_kernel(const float* __restrict__ g, const float* __restrict__ be, int N) {
    int c = threadIdx.x;
    if (c >= N) return;
    double s = 0.0, q = 0.0;
    for (int rb = 0; rb < 256; rb++) { s += (double)g_psum[rb * N + c]; q += (double)g_psq[rb * N + c]; }
    double mean = s / (double)BB;
    double var  = q / (double)BB - mean * mean;
    float sc = g[c] * rsqrtf((float)var + 1e-5f);
    g_scale[c] = sc;
    g_shift[c] = be[c] - (float)mean * sc;
}

// ---------------- final layer 64 -> 2 (with fused BN5+ReLU) ----------------
__global__ void __launch_bounds__(256) layer6_kernel(
    const float* __restrict__ w6, const float* __restrict__ b6, float* __restrict__ out)
{
    __shared__ float w[128];
    __shared__ float sc[64], sh[64];
    __shared__ float bb2[2];
    int t = threadIdx.x;
    if (t < 128) w[t] = w6[t];
    if (t < 64) { sc[t] = g_scale[t]; sh[t] = g_shift[t]; }
    if (t < 2) bb2[t] = b6[t];
    __syncthreads();
    int r = blockIdx.x * blockDim.x + t;
    if (r >= BB) return;
    const float* x = g_X5 + (size_t)r * 64;
    float a0 = bb2[0], a1 = bb2[1];
#pragma unroll
    for (int k = 0; k < 64; k++) {
        float v = fmaxf(0.0f, fmaf(x[k], sc[k], sh[k]));
        a0 = fmaf(v, w[2*k],   a0);
        a1 = fmaf(v, w[2*k+1], a1);
    }
    out[2*r]   = a0;
    out[2*r+1] = a1;
}

// ---------------- launch ----------------
extern "C" void kernel_launch(void* const* d_in, const int* in_sizes, int n_in,
                              void* d_out, int out_size) {
    const float* pos = (const float*)d_in[0];
    const float* mc  = (const float*)d_in[1];
    const float* mv  = (const float*)d_in[2];
    const float* w1 = (const float*)d_in[3];  const float* b1 = (const float*)d_in[4];
    const float* w2 = (const float*)d_in[5];  const float* b2 = (const float*)d_in[6];
    const float* w3 = (const float*)d_in[7];  const float* b3 = (const float*)d_in[8];
    const float* w4 = (const float*)d_in[9];  const float* b4 = (const float*)d_in[10];
    const float* w5 = (const float*)d_in[11]; const float* b5 = (const float*)d_in[12];
    const float* w6 = (const float*)d_in[13]; const float* b6 = (const float*)d_in[14];
    const float* g1 = (const float*)d_in[15]; const float* be1 = (const float*)d_in[16];
    const float* g2 = (const float*)d_in[17]; const float* be2 = (const float*)d_in[18];
    const float* g3 = (const float*)d_in[19]; const float* be3 = (const float*)d_in[20];
    const float* g4 = (const float*)d_in[21]; const float* be4 = (const float*)d_in[22];
    const float* g5 = (const float*)d_in[23]; const float* be5 = (const float*)d_in[24];
    float* out = (float*)d_out;

    float *X0p, *X1, *X2, *X3, *X4, *X5, *W1p;
    cudaGetSymbolAddress((void**)&X0p, g_X0p);
    cudaGetSymbolAddress((void**)&X1,  g_X1);
    cudaGetSymbolAddress((void**)&X2,  g_X2);
    cudaGetSymbolAddress((void**)&X3,  g_X3);
    cudaGetSymbolAddress((void**)&X4,  g_X4);
    cudaGetSymbolAddress((void**)&X5,  g_X5);
    cudaGetSymbolAddress((void**)&W1p, g_W1p);
    int *cCnt, *cStart, *qCnt, *qStart;
    cudaGetSymbolAddress((void**)&cCnt,   g_cellCount);
    cudaGetSymbolAddress((void**)&cStart, g_cellStart);
    cudaGetSymbolAddress((void**)&qCnt,   g_qCount);
    cudaGetSymbolAddress((void**)&qStart, g_qStart);

    const int SMEM128 = 6144 + 2*128*144 + 2*128*144 + 2048;
    const int SMEM64  = 6144 + 2*128*144 + 2*64*144  + 2048;
    cudaFuncSetAttribute(tcgemm_kernel<128,false>,
                         cudaFuncAttributeMaxDynamicSharedMemorySize, SMEM128);
    cudaFuncSetAttribute(tcgemm_kernel<128,true>,
                         cudaFuncAttributeMaxDynamicSharedMemorySize, SMEM128);
    cudaFuncSetAttribute(tcgemm_kernel<64,true>,
                         cudaFuncAttributeMaxDynamicSharedMemorySize, SMEM64);

    // grid build + query sort + KNN
    zero_cells_kernel<<<(NCELL + 255) / 256, 256>>>();
    count_kernel<<<(MM + 255) / 256, 256>>>(mc);
    qcount_kernel<<<(BB + 255) / 256, 256>>>(pos);
    scan_generic_kernel<<<1, 256>>>(cCnt, cStart);
    scan_generic_kernel<<<1, 256>>>(qCnt, qStart);
    scatter_kernel<<<(MM + 255) / 256, 256>>>(mc);
    qscatter_kernel<<<(BB + 255) / 256, 256>>>(pos);
    padw1_kernel<<<(128*128 + 255) / 256, 256>>>(w1);
    knn_kernel<<<BB / 256, 256>>>(pos, mc, mv, out + (size_t)BB * 2);

    // L1: 128(pad of 66) -> 128
    tcgemm_kernel<128,false><<<dim3(1, BB/128), 256, SMEM128>>>(X0p, W1p, b1, X1, 128, 128);
    bnfin_kernel<<<1, 128>>>(g1, be1, 128);

    // L2: 128 -> 256
    tcgemm_kernel<128,true><<<dim3(2, BB/128), 256, SMEM128>>>(X1, w2, b2, X2, 128, 256);
    bnfin_kernel<<<1, 256>>>(g2, be2, 256);

    // L3: 256 -> 512
    tcgemm_kernel<128,true><<<dim3(4, BB/128), 256, SMEM128>>>(X2, w3, b3, X3, 256, 512);
    bnfin_kernel<<<1, 512>>>(g3, be3, 512);

    // L4: 512 -> 128
    tcgemm_kernel<128,true><<<dim3(1, BB/128), 256, SMEM128>>>(X3, w4, b4, X4, 512, 128);
    bnfin_kernel<<<1, 128>>>(g4, be4, 128);

    // L5: 128 -> 64
    tcgemm_kernel<64,true><<<dim3(1, BB/128), 256, SMEM64>>>(X4, w5, b5, X5, 128, 64);
    bnfin_kernel<<<1, 64>>>(g5, be5, 64);

    // L6: 64 -> 2 (BN5+ReLU fused), writes x to out[0 : 2B]
    layer6_kernel<<<BB / 256, 256>>>(w6, b6, out);
}

// round 7
// speedup vs baseline: 1.5029x; 1.2945x over previous
#include <cuda_runtime.h>
#include <cuda_bf16.h>
#include <stdint.h>
#include <stddef.h>

#define BB 32768
#define MM 8192
#define GG 64
#define NCELL (GG*GG)

static __device__ __forceinline__ float f_inf() { return __int_as_float(0x7f800000); }

// ---------------- scratch (device globals; no allocation allowed) ----------------
__device__ float  g_X0p[BB*128];    // padded knn_feat (66 -> 128, zero pad)
__device__ float  g_X1[BB*128];
__device__ float  g_X2[BB*256];
__device__ float  g_X3[BB*512];
__device__ float  g_X4[BB*128];
__device__ float  g_X5[BB*64];
__device__ float  g_Xdummy[2048*512]; // probe-GEMM dead output
__device__ float  g_psum[256*512];
__device__ float  g_psq [256*512];
__device__ float  g_scale[512];
__device__ float  g_shift[512];
__device__ int    g_cellCount[NCELL];
__device__ int    g_cellFill [NCELL];
__device__ int    g_cellStart[NCELL+1];
__device__ int    g_qCount[NCELL];
__device__ int    g_qFill [NCELL];
__device__ int    g_qStart[NCELL+1];
__device__ int    g_qIdx[BB];
__device__ float4 g_packed[MM];     // (mx, my, mx^2+my^2, orig_idx)
__device__ float  g_W1p[128*128];   // zero-padded w1 (K 66->128)

// ---------------- PTX helpers (baseline PTX only: ldmatrix + mma.sync) ---------
static __device__ __forceinline__ uint32_t smem_u32(const void* p) {
    uint32_t a;
    asm("{ .reg .u64 t; cvta.to.shared.u64 t, %1; cvt.u32.u64 %0, t; }" : "=r"(a) : "l"(p));
    return a;
}
static __device__ __forceinline__ void ldsm4(uint32_t* r, uint32_t a) {
    asm volatile("ldmatrix.sync.aligned.m8n8.x4.shared.b16 {%0,%1,%2,%3}, [%4];"
        : "=r"(r[0]), "=r"(r[1]), "=r"(r[2]), "=r"(r[3]) : "r"(a));
}
static __device__ __forceinline__ void mma16816(float* d, const uint32_t* a,
                                                uint32_t b0, uint32_t b1) {
    asm volatile("mma.sync.aligned.m16n8k16.row.col.f32.bf16.bf16.f32 "
        "{%0,%1,%2,%3}, {%4,%5,%6,%7}, {%8,%9}, {%0,%1,%2,%3};"
        : "+f"(d[0]), "+f"(d[1]), "+f"(d[2]), "+f"(d[3])
        : "r"(a[0]), "r"(a[1]), "r"(a[2]), "r"(a[3]), "r"(b0), "r"(b1));
}
static __device__ __forceinline__ void bsplit(float a, __nv_bfloat16& h, __nv_bfloat16& l) {
    h = __float2bfloat16_rn(a);
    l = __float2bfloat16_rn(a - __bfloat162float(h));
}

// ---------------- grid build ----------------
__global__ void zero_cells_kernel() {
    int i = blockIdx.x*blockDim.x + threadIdx.x;
    if (i < NCELL) { g_cellCount[i] = 0; g_cellFill[i] = 0; g_qCount[i] = 0; g_qFill[i] = 0; }
}

__device__ __forceinline__ int cell_of(float v) {
    const float GMINF = -6.0f;
    const float INVH  = GG / 12.0f;
    int c = (int)floorf((v - GMINF) * INVH);
    return min(max(c, 0), GG-1);
}

__global__ void count_kernel(const float* __restrict__ mc) {
    int i = blockIdx.x*blockDim.x + threadIdx.x;
    if (i >= MM) return;
    int cx = cell_of(mc[2*i]);
    int cy = cell_of(mc[2*i+1]);
    atomicAdd(&g_cellCount[cy*GG + cx], 1);
}

__global__ void qcount_kernel(const float* __restrict__ pos) {
    int i = blockIdx.x*blockDim.x + threadIdx.x;
    if (i >= BB) return;
    int cx = cell_of(pos[2*i]);
    int cy = cell_of(pos[2*i+1]);
    atomicAdd(&g_qCount[cy*GG + cx], 1);
}

__global__ void scan_generic_kernel(const int* __restrict__ cnt, int* __restrict__ start) {
    __shared__ int sums[256];
    int t = threadIdx.x;
    const int per = NCELL / 256;
    int base = t * per;
    int s = 0;
    for (int i = 0; i < per; i++) s += cnt[base + i];
    sums[t] = s;
    __syncthreads();
    if (t == 0) {
        int acc = 0;
        for (int i = 0; i < 256; i++) { int v = sums[i]; sums[i] = acc; acc += v; }
    }
    __syncthreads();
    int off = sums[t];
    for (int i = 0; i < per; i++) { int v = cnt[base + i]; start[base + i] = off; off += v; }
    if (t == 255) start[NCELL] = off;
}

__global__ void scatter_kernel(const float* __restrict__ mc) {
    int i = blockIdx.x*blockDim.x + threadIdx.x;
    if (i >= MM) return;
    float x = mc[2*i], y = mc[2*i+1];
    int cx = cell_of(x), cy = cell_of(y);
    int c = cy*GG + cx;
    int slot = g_cellStart[c] + atomicAdd(&g_cellFill[c], 1);
    float sm = __fadd_rn(__fmul_rn(x, x), __fmul_rn(y, y));
    g_packed[slot] = make_float4(x, y, sm, __int_as_float(i));
}

__global__ void qscatter_kernel(const float* __restrict__ pos) {
    int i = blockIdx.x*blockDim.x + threadIdx.x;
    if (i >= BB) return;
    int cx = cell_of(pos[2*i]);
    int cy = cell_of(pos[2*i+1]);
    int c = cy*GG + cx;
    int slot = g_qStart[c] + atomicAdd(&g_qFill[c], 1);
    g_qIdx[slot] = i;
}

__global__ void padw1_kernel(const float* __restrict__ w1) {
    int i = blockIdx.x*blockDim.x + threadIdx.x;
    if (i >= 128*128) return;
    int row = i / 128, col = i % 128;
    g_W1p[i] = (row < 66) ? w1[row*128 + col] : 0.0f;
}

// ---------------- KNN (queries processed in cell-sorted order) ----------------
#define SCAN_RANGE(S_, E_)                                                        \
    for (int j_ = (S_); j_ < (E_); j_++) {                                        \
        float4 v_ = g_packed[j_];                                                 \
        float dot_ = __fmaf_rn(py, v_.y, __fmul_rn(px, v_.x));                    \
        float d2_  = __fmaf_rn(dot_, -2.0f, __fadd_rn(sp, v_.z));                 \
        int   mi_  = __float_as_int(v_.w);                                        \
        if (d2_ < key[15] || (d2_ == key[15] && mi_ < id[15])) {                  \
            float ck_ = d2_; int ci_ = mi_;                                       \
            _Pragma("unroll")                                                     \
            for (int t2_ = 0; t2_ < 16; t2_++) {                                  \
                bool sw_ = (ck_ < key[t2_]) || (ck_ == key[t2_] && ci_ < id[t2_]);\
                float tk_ = key[t2_]; int ti_ = id[t2_];                          \
                if (sw_) { key[t2_] = ck_; id[t2_] = ci_; ck_ = tk_; ci_ = ti_; } \
            }                                                                     \
        }                                                                         \
    }

__global__ void __launch_bounds__(256) knn_kernel(
    const float* __restrict__ pos, const float* __restrict__ mc,
    const float* __restrict__ mv, float* __restrict__ outKnn)
{
    const float GMINF = -6.0f;
    const float HCELL = 12.0f / GG;
    const float MARGIN = 1e-4f;
    int slot = blockIdx.x*blockDim.x + threadIdx.x;
    if (slot >= BB) return;
    int q = g_qIdx[slot];
    float px = pos[2*q], py = pos[2*q+1];
    float sp = __fadd_rn(__fmul_rn(px, px), __fmul_rn(py, py));

    float key[16]; int id[16];
#pragma unroll
    for (int i = 0; i < 16; i++) { key[i] = f_inf(); id[i] = 0x7fffffff; }

    int cx = cell_of(px), cy = cell_of(py);

    for (int R = 0;; R++) {
        int xlo = cx - R, xhi = cx + R, ylo = cy - R, yhi = cy + R;
        int xl = max(xlo, 0), xh = min(xhi, GG-1);
        int yl = max(ylo, 0), yh = min(yhi, GG-1);
        for (int yy = yl; yy <= yh; yy++) {
            if (yy == ylo || yy == yhi) {
                int s = g_cellStart[yy*GG + xl];
                int e = g_cellStart[yy*GG + xh + 1];
                SCAN_RANGE(s, e)
            } else {
                if (xlo >= 0) {
                    int s = g_cellStart[yy*GG + xlo];
                    int e = g_cellStart[yy*GG + xlo + 1];
                    SCAN_RANGE(s, e)
                }
                if (xhi <= GG-1) {
                    int s = g_cellStart[yy*GG + xhi];
                    int e = g_cellStart[yy*GG + xhi + 1];
                    SCAN_RANGE(s, e)
                }
            }
        }
        bool full = (xlo <= 0 && ylo <= 0 && xhi >= GG-1 && yhi >= GG-1);
        float x0 = GMINF + xlo * HCELL, x1 = GMINF + (xhi + 1) * HCELL;
        float y0 = GMINF + ylo * HCELL, y1 = GMINF + (yhi + 1) * HCELL;
        float db = fminf(fminf(px - x0, x1 - px), fminf(py - y0, y1 - py));
        if (full || (db > 0.0f && db*db > key[15] + MARGIN)) break;
    }

    float* o  = outKnn + (size_t)q * 66;
    float* xo = g_X0p  + (size_t)q * 128;
    o[0] = px; o[1] = py; xo[0] = px; xo[1] = py;
#pragma unroll
    for (int n = 0; n < 16; n++) {
        int mi = id[n];
        float ax = mc[2*mi], ay = mc[2*mi+1];
        float vx = mv[2*mi], vy = mv[2*mi+1];
        o[2+4*n] = ax; o[3+4*n] = ay; o[4+4*n] = vx; o[5+4*n] = vy;
        xo[2+4*n] = ax; xo[3+4*n] = ay; xo[4+4*n] = vx; xo[5+4*n] = vy;
    }
    for (int c = 66; c < 128; c += 2) { xo[c] = 0.0f; xo[c+1] = 0.0f; }
}

// ---------------- HMMA bf16x3 GEMM, BN+ReLU fused on A, fused col stats -------
template<int BNT, bool BNIN>
__global__ void __launch_bounds__(256, 1)
tcgemm_kernel(const float* __restrict__ A, const float* __restrict__ W,
              const float* __restrict__ bias, float* __restrict__ C,
              int K, int N)
{
    extern __shared__ char sm[];
    constexpr int NW  = BNT / 2;
    constexpr int NB8 = NW / 8;
    constexpr int NG  = NW / 16;
    constexpr int SS  = BNT + 4;
    constexpr int SM_BIAS = 64;
    constexpr int SM_SC   = 1024;
    constexpr int SM_SH   = 3072;
    constexpr int TIL = 6144;
    constexpr int AHI = TIL;
    constexpr int ALO = AHI + 128*144;
    constexpr int BHI = ALO + 128*144;
    constexpr int BLO = BHI + BNT*144;
    constexpr int TEND = BLO + BNT*144;
    constexpr int STGO = TIL;
    constexpr int RED  = TEND;

    uint32_t sbase = smem_u32(sm);
    int tid = threadIdx.x;
    int wid = tid >> 5, lane = tid & 31;
    int wm = wid & 3, wn = wid >> 2;
    int row0 = blockIdx.y * 128;
    int col0 = blockIdx.x * BNT;

    float* sBias = (float*)(sm + SM_BIAS);
    float* sSc   = (float*)(sm + SM_SC);
    float* sSh   = (float*)(sm + SM_SH);
    for (int i = tid; i < BNT; i += 256) sBias[i] = bias[col0 + i];
    if (BNIN) {
        for (int i = tid; i < K; i += 256) { sSc[i] = g_scale[i]; sSh[i] = g_shift[i]; }
    }
    __syncthreads();

    float d[2][NB8][4];
#pragma unroll
    for (int mt = 0; mt < 2; mt++)
#pragma unroll
        for (int nb = 0; nb < NB8; nb++)
#pragma unroll
            for (int j = 0; j < 4; j++) d[mt][nb][j] = 0.0f;

    const int nst = K / 64;
    for (int s = 0; s < nst; s++) {
        int k0 = s * 64;
#pragma unroll
        for (int it = 0; it < 8; it++) {
            int w = tid + it * 256;
            int m = w >> 4;
            int kc = (w & 15) * 4;
            float4 a = *(const float4*)(A + (size_t)(row0 + m) * K + k0 + kc);
            float av[4] = {a.x, a.y, a.z, a.w};
            if (BNIN) {
#pragma unroll
                for (int j = 0; j < 4; j++)
                    av[j] = fmaxf(0.0f, fmaf(av[j], sSc[k0+kc+j], sSh[k0+kc+j]));
            }
            __nv_bfloat16 h[4], l[4];
#pragma unroll
            for (int j = 0; j < 4; j++) bsplit(av[j], h[j], l[j]);
            uint32_t bo = (uint32_t)(m * 72 + kc) * 2;
            *(__nv_bfloat162*)(sm + AHI + bo)     = __halves2bfloat162(h[0], h[1]);
            *(__nv_bfloat162*)(sm + AHI + bo + 4) = __halves2bfloat162(h[2], h[3]);
            *(__nv_bfloat162*)(sm + ALO + bo)     = __halves2bfloat162(l[0], l[1]);
            *(__nv_bfloat162*)(sm + ALO + bo + 4) = __halves2bfloat162(l[2], l[3]);
        }
        for (int w = tid; w < 32 * (BNT/4); w += 256) {
            int kp = w / (BNT/4);
            int n0 = (w % (BNT/4)) * 4;
            int k  = kp * 2;
            const float* wp0 = W + (size_t)(k0 + k) * N + col0 + n0;
            float4 r0 = *(const float4*)wp0;
            float4 r1 = *(const float4*)(wp0 + N);
            float v0[4] = {r0.x, r0.y, r0.z, r0.w};
            float v1[4] = {r1.x, r1.y, r1.z, r1.w};
#pragma unroll
            for (int j = 0; j < 4; j++) {
                __nv_bfloat16 h0, l0, h1, l1;
                bsplit(v0[j], h0, l0);
                bsplit(v1[j], h1, l1);
                uint32_t bo = (uint32_t)((n0 + j) * 72 + k) * 2;
                *(__nv_bfloat162*)(sm + BHI + bo) = __halves2bfloat162(h0, h1);
                *(__nv_bfloat162*)(sm + BLO + bo) = __halves2bfloat162(l0, l1);
            }
        }
        __syncthreads();

        int lr = lane & 15, lc = lane >> 4;
#pragma unroll
        for (int kst = 0; kst < 4; kst++) {
            uint32_t koff = (uint32_t)(kst * 16 + lc * 8) * 2;
            uint32_t bh[NG][4], bl[NG][4];
#pragma unroll
            for (int g = 0; g < NG; g++) {
                uint32_t bo = (uint32_t)((wn*NW + g*16 + lr) * 72) * 2 + koff;
                ldsm4(bh[g], sbase + BHI + bo);
                ldsm4(bl[g], sbase + BLO + bo);
            }
#pragma unroll
            for (int mt = 0; mt < 2; mt++) {
                uint32_t ao = (uint32_t)((wm*32 + mt*16 + lr) * 72) * 2 + koff;
                uint32_t ah[4], al[4];
                ldsm4(ah, sbase + AHI + ao);
                ldsm4(al, sbase + ALO + ao);
#pragma unroll
                for (int g = 0; g < NG; g++) {
                    mma16816(d[mt][2*g],   ah, bh[g][0], bh[g][2]);
                    mma16816(d[mt][2*g],   ah, bl[g][0], bl[g][2]);
                    mma16816(d[mt][2*g],   al, bh[g][0], bh[g][2]);
                    mma16816(d[mt][2*g+1], ah, bh[g][1], bh[g][3]);
                    mma16816(d[mt][2*g+1], ah, bl[g][1], bl[g][3]);
                    mma16816(d[mt][2*g+1], al, bh[g][1], bh[g][3]);
                }
            }
        }
        __syncthreads();
    }

    float* stg = (float*)(sm + STGO);
    float* red = (float*)(sm + RED);
#pragma unroll
    for (int mt = 0; mt < 2; mt++)
#pragma unroll
        for (int nb = 0; nb < NB8; nb++) {
            int col = wn*NW + nb*8 + 2*(lane & 3);
            int row = wm*32 + mt*16 + (lane >> 2);
            float b0 = sBias[col], b1 = sBias[col+1];
            stg[row*SS + col]       = d[mt][nb][0] + b0;
            stg[row*SS + col + 1]   = d[mt][nb][1] + b1;
            stg[(row+8)*SS + col]   = d[mt][nb][2] + b0;
            stg[(row+8)*SS + col+1] = d[mt][nb][3] + b1;
        }
    __syncthreads();

    for (int idx = tid; idx < 128 * (BNT/4); idx += 256) {
        int m  = idx / (BNT/4);
        int j4 = (idx % (BNT/4)) * 4;
        float4 v;
        v.x = stg[m*SS + j4 + 0];
        v.y = stg[m*SS + j4 + 1];
        v.z = stg[m*SS + j4 + 2];
        v.w = stg[m*SS + j4 + 3];
        *(float4*)(C + (size_t)(row0 + m) * N + col0 + j4) = v;
    }

#pragma unroll
    for (int c = 0; c < BNT/32; c++) {
        int j = tid & 31, seg = tid >> 5;
        float s2 = 0.0f, q2 = 0.0f;
        for (int r2 = 0; r2 < 16; r2++) {
            float v = stg[(seg*16 + r2) * SS + c*32 + j];
            s2 += v;
            q2 = fmaf(v, v, q2);
        }
        red[seg*32 + j] = s2;
        red[256 + seg*32 + j] = q2;
        __syncthreads();
        if (tid < 32) {
            float s = 0.0f, q = 0.0f;
            for (int u = 0; u < 8; u++) { s += red[u*32 + tid]; q += red[256 + u*32 + tid]; }
            g_psum[blockIdx.y * N + col0 + c*32 + tid] = s;
            g_psq [blockIdx.y * N + col0 + c*32 + tid] = q;
        }
        __syncthreads();
    }
}

// ---------------- BN finalize (parallel over column blocks) ----------------
__global__ void bnfin_kernel(const float* __restrict__ g, const float* __restrict__ be, int N) {
    int c = blockIdx.x * 64 + threadIdx.x;
    if (c >= N) return;
    double s = 0.0, q = 0.0;
    for (int rb = 0; rb < 256; rb++) { s += (double)g_psum[rb * N + c]; q += (double)g_psq[rb * N + c]; }
    double mean = s / (double)BB;
    double var  = q / (double)BB - mean * mean;
    float sc = g[c] * rsqrtf((float)var + 1e-5f);
    g_scale[c] = sc;
    g_shift[c] = be[c] - (float)mean * sc;
}

// ---------------- final layer 64 -> 2 (with fused BN5+ReLU) ----------------
__global__ void __launch_bounds__(256) layer6_kernel(
    const float* __restrict__ w6, const float* __restrict__ b6, float* __restrict__ out)
{
    __shared__ float w[128];
    __shared__ float sc[64], sh[64];
    __shared__ float bb2[2];
    int t = threadIdx.x;
    if (t < 128) w[t] = w6[t];
    if (t < 64) { sc[t] = g_scale[t]; sh[t] = g_shift[t]; }
    if (t < 2) bb2[t] = b6[t];
    __syncthreads();
    int r = blockIdx.x * blockDim.x + t;
    if (r >= BB) return;
    const float* x = g_X5 + (size_t)r * 64;
    float a0 = bb2[0], a1 = bb2[1];
#pragma unroll
    for (int k = 0; k < 64; k++) {
        float v = fmaxf(0.0f, fmaf(x[k], sc[k], sh[k]));
        a0 = fmaf(v, w[2*k],   a0);
        a1 = fmaf(v, w[2*k+1], a1);
    }
    out[2*r]   = a0;
    out[2*r+1] = a1;
}

// ---------------- launch ----------------
extern "C" void kernel_launch(void* const* d_in, const int* in_sizes, int n_in,
                              void* d_out, int out_size) {
    const float* pos = (const float*)d_in[0];
    const float* mc  = (const float*)d_in[1];
    const float* mv  = (const float*)d_in[2];
    const float* w1 = (const float*)d_in[3];  const float* b1 = (const float*)d_in[4];
    const float* w2 = (const float*)d_in[5];  const float* b2 = (const float*)d_in[6];
    const float* w3 = (const float*)d_in[7];  const float* b3 = (const float*)d_in[8];
    const float* w4 = (const float*)d_in[9];  const float* b4 = (const float*)d_in[10];
    const float* w5 = (const float*)d_in[11]; const float* b5 = (const float*)d_in[12];
    const float* w6 = (const float*)d_in[13]; const float* b6 = (const float*)d_in[14];
    const float* g1 = (const float*)d_in[15]; const float* be1 = (const float*)d_in[16];
    const float* g2 = (const float*)d_in[17]; const float* be2 = (const float*)d_in[18];
    const float* g3 = (const float*)d_in[19]; const float* be3 = (const float*)d_in[20];
    const float* g4 = (const float*)d_in[21]; const float* be4 = (const float*)d_in[22];
    const float* g5 = (const float*)d_in[23]; const float* be5 = (const float*)d_in[24];
    float* out = (float*)d_out;

    float *X0p, *X1, *X2, *X3, *X4, *X5, *Xd, *W1p;
    cudaGetSymbolAddress((void**)&X0p, g_X0p);
    cudaGetSymbolAddress((void**)&X1,  g_X1);
    cudaGetSymbolAddress((void**)&X2,  g_X2);
    cudaGetSymbolAddress((void**)&X3,  g_X3);
    cudaGetSymbolAddress((void**)&X4,  g_X4);
    cudaGetSymbolAddress((void**)&X5,  g_X5);
    cudaGetSymbolAddress((void**)&Xd,  g_Xdummy);
    cudaGetSymbolAddress((void**)&W1p, g_W1p);
    int *cCnt, *cStart, *qCnt, *qStart;
    cudaGetSymbolAddress((void**)&cCnt,   g_cellCount);
    cudaGetSymbolAddress((void**)&cStart, g_cellStart);
    cudaGetSymbolAddress((void**)&qCnt,   g_qCount);
    cudaGetSymbolAddress((void**)&qStart, g_qStart);

    const int SMEM128 = 6144 + 2*128*144 + 2*128*144 + 2048;
    const int SMEM64  = 6144 + 2*128*144 + 2*64*144  + 2048;
    cudaFuncSetAttribute(tcgemm_kernel<128,false>,
                         cudaFuncAttributeMaxDynamicSharedMemorySize, SMEM128);
    cudaFuncSetAttribute(tcgemm_kernel<128,true>,
                         cudaFuncAttributeMaxDynamicSharedMemorySize, SMEM128);
    cudaFuncSetAttribute(tcgemm_kernel<64,true>,
                         cudaFuncAttributeMaxDynamicSharedMemorySize, SMEM64);

    // launches 1-3
    zero_cells_kernel<<<(NCELL + 255) / 256, 256>>>();
    count_kernel<<<(MM + 255) / 256, 256>>>(mc);
    qcount_kernel<<<(BB + 255) / 256, 256>>>(pos);

    // launch 4 = PROFILING PROBE: 1/16-size L3-shaped GEMM into dead buffer.
    // Reads stale g_X2 (deterministic-output-safe: g_Xdummy never read; its
    // g_psum/g_psq rows are fully overwritten by the real L1 GEMM below).
    tcgemm_kernel<128,true><<<dim3(4, 16), 256, SMEM128>>>(X2, w3, b3, Xd, 256, 512);

    scan_generic_kernel<<<1, 256>>>(cCnt, cStart);
    scan_generic_kernel<<<1, 256>>>(qCnt, qStart);
    scatter_kernel<<<(MM + 255) / 256, 256>>>(mc);
    qscatter_kernel<<<(BB + 255) / 256, 256>>>(pos);
    padw1_kernel<<<(128*128 + 255) / 256, 256>>>(w1);
    knn_kernel<<<BB / 256, 256>>>(pos, mc, mv, out + (size_t)BB * 2);

    // L1: 128(pad of 66) -> 128
    tcgemm_kernel<128,false><<<dim3(1, BB/128), 256, SMEM128>>>(X0p, W1p, b1, X1, 128, 128);
    bnfin_kernel<<<2, 64>>>(g1, be1, 128);

    // L2: 128 -> 256
    tcgemm_kernel<128,true><<<dim3(2, BB/128), 256, SMEM128>>>(X1, w2, b2, X2, 128, 256);
    bnfin_kernel<<<4, 64>>>(g2, be2, 256);

    // L3: 256 -> 512
    tcgemm_kernel<128,true><<<dim3(4, BB/128), 256, SMEM128>>>(X2, w3, b3, X3, 256, 512);
    bnfin_kernel<<<8, 64>>>(g3, be3, 512);

    // L4: 512 -> 128
    tcgemm_kernel<128,true><<<dim3(1, BB/128), 256, SMEM128>>>(X3, w4, b4, X4, 512, 128);
    bnfin_kernel<<<2, 64>>>(g4, be4, 128);

    // L5: 128 -> 64
    tcgemm_kernel<64,true><<<dim3(1, BB/128), 256, SMEM64>>>(X4, w5, b5, X5, 128, 64);
    bnfin_kernel<<<1, 64>>>(g5, be5, 64);

    // L6: 64 -> 2 (BN5+ReLU fused), writes x to out[0 : 2B]
    layer6_kernel<<<BB / 256, 256>>>(w6, b6, out);
}